// round 5
// baseline (speedup 1.0000x reference)
#include <cuda_runtime.h>
#include <cstdint>

#define BATCH 512
#define SEQ   512
#define EMB   128
#define HID   64
#define GATES 256   // 4*HID
#define VOCAB 50000

// 51.2 MB token->xproj table: table[v][g] = dot(emb[v], Wih0[g]) + bih0[g] + bhh0[g]
__device__ float g_tab[(size_t)VOCAB * GATES];

// ---------------- packed f32x2 / misc helpers ----------------
static __device__ __forceinline__ unsigned long long pk2(float lo, float hi) {
    unsigned long long v;
    asm("mov.b64 %0, {%1, %2};" : "=l"(v) : "f"(lo), "f"(hi));
    return v;
}
static __device__ __forceinline__ void upk2(unsigned long long v, float& lo, float& hi) {
    asm("mov.b64 {%0, %1}, %2;" : "=f"(lo), "=f"(hi) : "l"(v));
}
static __device__ __forceinline__ void fma2(unsigned long long& a,
                                            unsigned long long x,
                                            unsigned long long w) {
    asm("fma.rn.f32x2 %0, %1, %2, %0;" : "+l"(a) : "l"(x), "l"(w));
}
static __device__ __forceinline__ float tanh_f(float x) {
    float y;
    asm("tanh.approx.f32 %0, %1;" : "=f"(y) : "f"(x));
    return y;
}
static __device__ __forceinline__ float sig_f(float x) {
    return fmaf(0.5f, tanh_f(0.5f * x), 0.5f);
}
static __device__ __forceinline__ uint32_t smem_u32(const void* p) {
    uint32_t a;
    asm("{ .reg .u64 t; cvta.to.shared.u64 t, %1; cvt.u32.u64 %0, t; }"
        : "=r"(a) : "l"(p));
    return a;
}
static __device__ __forceinline__ void cp_async4(uint32_t dst, const void* src) {
    asm volatile("cp.async.ca.shared.global [%0], [%1], 4;" :: "r"(dst), "l"(src));
}
#define CP_COMMIT() asm volatile("cp.async.commit_group;" ::: "memory")
#define CP_WAIT0()  asm volatile("cp.async.wait_group 0;" ::: "memory")
#define CP_WAITALL() asm volatile("cp.async.wait_all;" ::: "memory")

// ======================================================================
// Kernel 1: token table build. table[v][g] = emb[v] . Wih0[g] + b0[g].
// ======================================================================
#define XT_STRIDE 136

__global__ void __launch_bounds__(256, 2)
k_table(const float* __restrict__ emb,
        const float* __restrict__ Wih0,
        const float* __restrict__ bih0,
        const float* __restrict__ bhh0,
        float* __restrict__ tab)
{
    __shared__ float xs[16 * XT_STRIDE];

    const int tid  = threadIdx.x;
    const int gl   = tid >> 1;
    const int half = tid & 1;
    const int g    = blockIdx.y * 128 + gl;

    unsigned long long w[32];
#pragma unroll
    for (int j = 0; j < 16; ++j) {
        ulonglong2 v = *(const ulonglong2*)&Wih0[g * EMB + half * 64 + j * 4];
        w[2 * j] = v.x;  w[2 * j + 1] = v.y;
    }
    const float b0 = (half == 0) ? (__ldg(&bih0[g]) + __ldg(&bhh0[g])) : 0.f;

    const int v0 = blockIdx.x * 128;

#pragma unroll 1
    for (int tile = 0; tile < 8; ++tile) {
        const int vbase = v0 + tile * 16;
        if (vbase >= VOCAB) break;
        const int rows = min(16, VOCAB - vbase);

        __syncthreads();
        for (int j = tid; j < rows * 32; j += 256) {
            const int r = j >> 5, k4 = j & 31;
            const int dst = r * XT_STRIDE + (k4 < 16 ? k4 * 4 : 68 + (k4 - 16) * 4);
            *(float4*)&xs[dst] = *(const float4*)&emb[(size_t)(vbase + r) * EMB + k4 * 4];
        }
        __syncthreads();

        unsigned long long acc[16];
#pragma unroll
        for (int r = 0; r < 16; ++r) acc[r] = pk2(b0, 0.f);

#pragma unroll
        for (int kc = 0; kc < 16; ++kc) {
#pragma unroll
            for (int r = 0; r < 16; ++r) {
                const ulonglong2 x = *(const ulonglong2*)&xs[r * XT_STRIDE + half * 68 + kc * 4];
                fma2(acc[r], x.x, w[2 * kc]);
                fma2(acc[r], x.y, w[2 * kc + 1]);
            }
        }
#pragma unroll
        for (int r = 0; r < 16; ++r) {
            float lo, hi; upk2(acc[r], lo, hi);
            float s = lo + hi;
            s += __shfl_xor_sync(0xFFFFFFFFu, s, 1);
            if (half == 0 && r < rows)
                tab[(size_t)(vbase + r) * GATES + g] = s;
        }
    }
}

// ======================================================================
// Kernel 2: fused 2-layer LSTM scan, layer-pipelined (layer1 lags by 1
// step). 128 blocks x 512 threads; block owns batch rows 4b..4b+3.
// Per iter t (t = 0..SEQ):
//   Phase G: gates0(t) [if t<SEQ] and gates1(t-1) [if t>=1]; both read
//            h0(t-1), h1(t-2). Partials stored per (gate,half) pair.
//   bar
//   Phase E: tid<256 -> layer0 elem (h0(t)); tid>=256 -> layer1 elem
//            (h1(t-1)).
//   bar
// xproj rows prefetched one step ahead via cp.async into smem.
// ======================================================================
#define HS 136   // h row stride (floats): half0 at +0, half1 at +68

__global__ void __launch_bounds__(512, 1)
k_scan(const int* __restrict__ seq32,
       const float* __restrict__ tab,
       const float* __restrict__ Whh0, const float* __restrict__ Wih1,
       const float* __restrict__ Whh1,
       const float* __restrict__ bih1, const float* __restrict__ bhh1,
       const float* __restrict__ Wfc,  const float* __restrict__ bfc,
       float* __restrict__ out)
{
    __shared__ float h0s[4 * HS];
    __shared__ float h1s[4 * HS];
    __shared__ float gA[4 * GATES * 2];     // [(r*GATES+g)*2 + half]
    __shared__ float gB[4 * GATES * 2];
    __shared__ float sx[2][4 * GATES];      // xproj double buffer [r*GATES+g]
    __shared__ int   tokS[SEQ * 4];         // tokens [t][r]

    const int tid  = threadIdx.x;
    const int g    = tid >> 1;
    const int half = tid & 1;
    const int row0 = blockIdx.x * 4;

    // ---- weights: 3 half-rows of 32 floats each -> 48 f32x2 = 96 regs
    unsigned long long w0[16], wi1[16], wh1[16];
#pragma unroll
    for (int j = 0; j < 8; ++j) {
        ulonglong2 v;
        v = *(const ulonglong2*)&Whh0[g * HID + half * 32 + j * 4];
        w0[2 * j] = v.x;  w0[2 * j + 1] = v.y;
        v = *(const ulonglong2*)&Wih1[g * HID + half * 32 + j * 4];
        wi1[2 * j] = v.x; wi1[2 * j + 1] = v.y;
        v = *(const ulonglong2*)&Whh1[g * HID + half * 32 + j * 4];
        wh1[2 * j] = v.x; wh1[2 * j + 1] = v.y;
    }
    const float b1 = (half == 0) ? (__ldg(&bih1[g]) + __ldg(&bhh1[g])) : 0.f;

    // int64 vs int32 input_seq detection
    const bool is64 = ((__ldg(seq32 + 1) | __ldg(seq32 + 3) | __ldg(seq32 + 5) |
                        __ldg(seq32 + 7) | __ldg(seq32 + 9) | __ldg(seq32 + 11) |
                        __ldg(seq32 + 13) | __ldg(seq32 + 15)) == 0);

    // ---- stage tokens: tokS[t*4+r] = seq[row0+r][t]
    {
        const int t = tid;   // SEQ == 512 == blockDim
#pragma unroll
        for (int r = 0; r < 4; ++r) {
            const int src = (row0 + r) * SEQ + t;
            tokS[t * 4 + r] = is64 ? __ldg(seq32 + 2 * src) : __ldg(seq32 + src);
        }
    }
    for (int j = tid; j < 4 * HS; j += 512) {
        h0s[j] = 0.f;
        h1s[j] = 0.f;
    }
    __syncthreads();   // tokS / h ready

    const uint32_t sx_u32 = smem_u32(&sx[0][0]);

    // ---- initial xproj(0) into sx[0]
    {
        const int e0 = tid, e1 = tid + 512;
        const int r0 = e0 >> 8, g0 = e0 & 255;
        const int r1 = e1 >> 8, g1 = e1 & 255;
        cp_async4(sx_u32 + (uint32_t)e0 * 4,
                  &tab[(size_t)tokS[0 * 4 + r0] * GATES + g0]);
        cp_async4(sx_u32 + (uint32_t)e1 * 4,
                  &tab[(size_t)tokS[0 * 4 + r1] * GATES + g1]);
        CP_WAITALL();
    }
    __syncthreads();

    const int rr = tid >> 6;          // for tid<256: row of layer0 elem
    const int u  = tid & 63;
    const int w1t = tid - 256;        // for tid>=256
    const int rr1 = (w1t >> 6) & 3;
    float c0 = 0.f, c1 = 0.f;

    for (int t = 0; t <= SEQ; ++t) {
        const int cur = t & 1, nxt = cur ^ 1;
        const bool do0 = (t < SEQ);
        const bool do1 = (t >= 1);

        // ---- issue prefetch of xproj(t+1) into sx[nxt]
        if (t + 1 < SEQ) {
            const int e0 = tid, e1 = tid + 512;
            const int r0 = e0 >> 8, g0 = e0 & 255;
            const int r1 = e1 >> 8, g1 = e1 & 255;
            cp_async4(sx_u32 + (uint32_t)(nxt * 1024 + e0) * 4,
                      &tab[(size_t)tokS[(t + 1) * 4 + r0] * GATES + g0]);
            cp_async4(sx_u32 + (uint32_t)(nxt * 1024 + e1) * 4,
                      &tab[(size_t)tokS[(t + 1) * 4 + r1] * GATES + g1]);
            CP_COMMIT();
        }

        // ---- Phase G: layer0 gates(t)
        if (do0) {
            unsigned long long a0[4];
#pragma unroll
            for (int r = 0; r < 4; ++r) {
                float xi = 0.f;
                if (half == 0) xi = sx[cur][r * GATES + g];
                a0[r] = pk2(xi, 0.f);
            }
#pragma unroll
            for (int kc = 0; kc < 8; ++kc) {
#pragma unroll
                for (int r = 0; r < 4; ++r) {
                    const ulonglong2 h = *(const ulonglong2*)&h0s[r * HS + half * 68 + kc * 4];
                    fma2(a0[r], h.x, w0[2 * kc]);
                    fma2(a0[r], h.y, w0[2 * kc + 1]);
                }
            }
#pragma unroll
            for (int r = 0; r < 4; ++r) {
                float lo, hi; upk2(a0[r], lo, hi);
                gA[(r * GATES + g) * 2 + half] = lo + hi;
            }
        }
        // ---- Phase G: layer1 gates(t-1)
        if (do1) {
            unsigned long long a1[4];
#pragma unroll
            for (int r = 0; r < 4; ++r) a1[r] = pk2(b1, 0.f);
#pragma unroll
            for (int kc = 0; kc < 8; ++kc) {
#pragma unroll
                for (int r = 0; r < 4; ++r) {
                    const ulonglong2 h0v = *(const ulonglong2*)&h0s[r * HS + half * 68 + kc * 4];
                    fma2(a1[r], h0v.x, wi1[2 * kc]);
                    fma2(a1[r], h0v.y, wi1[2 * kc + 1]);
                    const ulonglong2 h1v = *(const ulonglong2*)&h1s[r * HS + half * 68 + kc * 4];
                    fma2(a1[r], h1v.x, wh1[2 * kc]);
                    fma2(a1[r], h1v.y, wh1[2 * kc + 1]);
                }
            }
#pragma unroll
            for (int r = 0; r < 4; ++r) {
                float lo, hi; upk2(a1[r], lo, hi);
                gB[(r * GATES + g) * 2 + half] = lo + hi;
            }
        }
        __syncthreads();   // (1) gA/gB ready; h reads done

        // ---- Phase E
        if (tid < 256) {
            if (do0) {
                const float2* gr = (const float2*)(gA + rr * GATES * 2);
                const float2 vi = gr[u],        vf = gr[64 + u];
                const float2 vg = gr[128 + u],  vo = gr[192 + u];
                float gi = sig_f(vi.x + vi.y);
                float gf = sig_f(vf.x + vf.y);
                float gg = tanh_f(vg.x + vg.y);
                float go = sig_f(vo.x + vo.y);
                c0 = gf * c0 + gi * gg;
                h0s[rr * HS + (u >> 5) * 68 + (u & 31)] = go * tanh_f(c0);
            }
        } else {
            if (do1) {
                const float2* gr = (const float2*)(gB + rr1 * GATES * 2);
                const float2 vi = gr[u],        vf = gr[64 + u];
                const float2 vg = gr[128 + u],  vo = gr[192 + u];
                float gi = sig_f(vi.x + vi.y);
                float gf = sig_f(vf.x + vf.y);
                float gg = tanh_f(vg.x + vg.y);
                float go = sig_f(vo.x + vo.y);
                c1 = gf * c1 + gi * gg;
                h1s[rr1 * HS + (u >> 5) * 68 + (u & 31)] = go * tanh_f(c1);
            }
        }
        CP_WAIT0();
        __syncthreads();   // (2) h0(t)/h1(t-1) + sx[nxt] published
    }

    // ---- Final FC + sigmoid on h1(SEQ-1)
    if (tid < 8) {
        int r = tid >> 1, o = tid & 1;
        float a = __ldg(&bfc[o]);
        for (int k = 0; k < HID; ++k)
            a = fmaf(h1s[r * HS + (k >> 5) * 68 + (k & 31)],
                     __ldg(&Wfc[o * HID + k]), a);
        out[(row0 + r) * 2 + o] = sig_f(a);
    }
}

// ======================================================================
extern "C" void kernel_launch(void* const* d_in, const int* in_sizes, int n_in,
                              void* d_out, int out_size) {
    const int*   seq32 = (const int*)d_in[0];
    const float* emb   = (const float*)d_in[1];
    const float* Wih0  = (const float*)d_in[2];
    const float* Whh0  = (const float*)d_in[3];
    const float* bih0  = (const float*)d_in[4];
    const float* bhh0  = (const float*)d_in[5];
    const float* Wih1  = (const float*)d_in[6];
    const float* Whh1  = (const float*)d_in[7];
    const float* bih1  = (const float*)d_in[8];
    const float* bhh1  = (const float*)d_in[9];
    const float* Wfc   = (const float*)d_in[10];
    const float* bfc   = (const float*)d_in[11];
    float* out = (float*)d_out;

    float* tab = nullptr;
    cudaGetSymbolAddress((void**)&tab, g_tab);

    dim3 gtab((VOCAB + 127) / 128, 2);
    k_table<<<gtab, 256>>>(emb, Wih0, bih0, bhh0, tab);
    k_scan<<<BATCH / 4, 512>>>(seq32, tab, Whh0, Wih1, Whh1,
                               bih1, bhh1, Wfc, bfc, out);
}